// round 1
// baseline (speedup 1.0000x reference)
#include <cuda_runtime.h>
#include <cuda_bf16.h>

#define BATCH 32
#define CIN   256
#define CC    64
#define PT    196     // 14*14
#define HT    14
#define PS    4096    // 64*64
#define HS    64
#define NGROUP 32     // groups of 2 channels

// ---------------- scratch (device globals; allocation-free) ----------------
__device__ float g_sraw[(size_t)BATCH*CC*PS];   // raw search conv1x1 (pre-GN)
__device__ float g_corr[(size_t)BATCH*CC*PS];   // global+local correlation
__device__ float g_y   [(size_t)BATCH*CC*PS];   // conv3x3 output (pre-GN)
__device__ float g_tker[(size_t)BATCH*CC*49];   // pooled 7x7 template kernels
__device__ float g_tglob[(size_t)BATCH*CC];     // template global means
__device__ float g_smean[BATCH*NGROUP];
__device__ float g_srstd[BATCH*NGROUP];
__device__ float g_pmean[BATCH*NGROUP];
__device__ float g_prstd[BATCH*NGROUP];

// ---------------- 1) template branch: conv1x1 + GN + relu + pools ----------
// grid (32 batch, 32 group), 128 threads
__global__ void k_template(const float* __restrict__ tf, const float* __restrict__ wt,
                           const float* __restrict__ gw, const float* __restrict__ gb) {
    int b = blockIdx.x, g = blockIdx.y;
    __shared__ float tv[392];
    __shared__ float r1[128], r2[128];
    __shared__ float s_mean, s_rstd;
    int tid = threadIdx.x;
    const float* x = tf + (size_t)b * CIN * PT;

    for (int idx = tid; idx < 392; idx += 128) {
        int c = idx / PT, p = idx - c * PT;
        const float* wr = wt + (g * 2 + c) * CIN;
        float acc = 0.f;
        #pragma unroll 8
        for (int ci = 0; ci < CIN; ci++) acc += x[ci * PT + p] * wr[ci];
        tv[idx] = acc;
    }
    __syncthreads();

    float s = 0.f, ss = 0.f;
    for (int idx = tid; idx < 392; idx += 128) { float v = tv[idx]; s += v; ss += v * v; }
    r1[tid] = s; r2[tid] = ss;
    __syncthreads();
    for (int o = 64; o > 0; o >>= 1) {
        if (tid < o) { r1[tid] += r1[tid + o]; r2[tid] += r2[tid + o]; }
        __syncthreads();
    }
    if (tid == 0) {
        float m = r1[0] * (1.f / 392.f);
        float var = r2[0] * (1.f / 392.f) - m * m;
        s_mean = m; s_rstd = rsqrtf(var + 1e-5f);
    }
    __syncthreads();

    for (int idx = tid; idx < 392; idx += 128) {
        int c = idx / PT;
        float v = (tv[idx] - s_mean) * s_rstd * gw[g * 2 + c] + gb[g * 2 + c];
        tv[idx] = fmaxf(v, 0.f);
    }
    __syncthreads();

    // 2x2 avg pool -> 7x7 kernel
    if (tid < 98) {
        int c = tid / 49, cell = tid - c * 49;
        int i = cell / 7, j = cell - i * 7;
        int base = c * PT + (2 * i) * HT + 2 * j;
        float v = 0.25f * (tv[base] + tv[base + 1] + tv[base + HT] + tv[base + HT + 1]);
        g_tker[((size_t)b * CC + g * 2 + c) * 49 + cell] = v;
    }
    // global mean
    if (tid < 2) {
        float acc = 0.f;
        for (int p = 0; p < PT; p++) acc += tv[tid * PT + p];
        g_tglob[(size_t)b * CC + g * 2 + tid] = acc * (1.f / 196.f);
    }
}

// ---------------- 2) search conv1x1 GEMM: [64,256]x[256,4096] per batch ----
// grid (32 px-tiles of 128, 32 batch), 256 threads, 4 out x 8 px per thread
__global__ void __launch_bounds__(256) k_sgemm(const float* __restrict__ sf,
                                               const float* __restrict__ ws) {
    int b = blockIdx.y;
    int p0 = blockIdx.x * 128;
    __shared__ float As[16][68];    // [k][o], padded
    __shared__ float Bs[16][128];   // [k][p]
    int tid = threadIdx.x;
    int ty = tid >> 4;              // 0..15 -> outs ty*4..+3
    int tx = tid & 15;              // px tx*8..+7
    float acc[4][8];
    #pragma unroll
    for (int i = 0; i < 4; i++)
        #pragma unroll
        for (int j = 0; j < 8; j++) acc[i][j] = 0.f;

    const float* xb = sf + (size_t)b * CIN * PS + p0;

    for (int k0 = 0; k0 < CIN; k0 += 16) {
        __syncthreads();
        // A: coalesced rows of w_s, store transposed [k][o]
        for (int i = tid; i < 1024; i += 256) {
            int o = i >> 4, k = i & 15;
            As[k][o] = ws[o * CIN + k0 + k];
        }
        // B: float4 coalesced
        for (int i = tid; i < 512; i += 256) {
            int k = i >> 5, p4 = i & 31;
            ((float4*)Bs[k])[p4] =
                ((const float4*)(xb + (size_t)(k0 + k) * PS))[p4];
        }
        __syncthreads();
        #pragma unroll
        for (int k = 0; k < 16; k++) {
            float4 a  = *(const float4*)&As[k][ty * 4];
            float4 b0 = *(const float4*)&Bs[k][tx * 8];
            float4 b1 = *(const float4*)&Bs[k][tx * 8 + 4];
            float av[4] = {a.x, a.y, a.z, a.w};
            float bv[8] = {b0.x, b0.y, b0.z, b0.w, b1.x, b1.y, b1.z, b1.w};
            #pragma unroll
            for (int i = 0; i < 4; i++)
                #pragma unroll
                for (int j = 0; j < 8; j++) acc[i][j] += av[i] * bv[j];
        }
    }
    #pragma unroll
    for (int i = 0; i < 4; i++) {
        int o = ty * 4 + i;
        float* dst = g_sraw + ((size_t)b * CC + o) * PS + p0 + tx * 8;
        *(float4*)dst       = make_float4(acc[i][0], acc[i][1], acc[i][2], acc[i][3]);
        *(float4*)(dst + 4) = make_float4(acc[i][4], acc[i][5], acc[i][6], acc[i][7]);
    }
}

// ---------------- 3/6) GN stats: per (b,group) over 2 channels x 4096 ------
// grid 1024, 256 threads. which=0 -> g_sraw, which=1 -> g_y
__global__ void k_stats(int which) {
    const float* buf = which ? g_y : g_sraw;
    float* mean = which ? g_pmean : g_smean;
    float* rstd = which ? g_prstd : g_srstd;
    int bg = blockIdx.x;
    const float* x = buf + (size_t)bg * 2 * PS;
    int tid = threadIdx.x;
    float s = 0.f, ss = 0.f;
    for (int i = tid; i < 2 * PS; i += 256) { float v = x[i]; s += v; ss += v * v; }
    __shared__ float r1[256], r2[256];
    r1[tid] = s; r2[tid] = ss;
    __syncthreads();
    for (int o = 128; o > 0; o >>= 1) {
        if (tid < o) { r1[tid] += r1[tid + o]; r2[tid] += r2[tid + o]; }
        __syncthreads();
    }
    if (tid == 0) {
        float m = r1[0] * (1.f / (2.f * PS));
        float var = r2[0] * (1.f / (2.f * PS)) - m * m;
        mean[bg] = m; rstd[bg] = rsqrtf(var + 1e-5f);
    }
}

// ---------------- 4) corr = global + 7x7 depthwise local -------------------
// grid (4 tiles of 32x32, 64 ch, 32 batch), 256 threads, 4 px per thread
__global__ void __launch_bounds__(256) k_corr(const float* __restrict__ gnw,
                                              const float* __restrict__ gnb) {
    int tile = blockIdx.x, c = blockIdx.y, b = blockIdx.z;
    int ty0 = (tile >> 1) * 32, tx0 = (tile & 1) * 32;
    __shared__ float sm[38 * 38];
    __shared__ float kw[49];
    int tid = threadIdx.x;
    int bg = b * NGROUP + (c >> 1);
    float mean = g_smean[bg], rstd = g_srstd[bg];
    float gamma = gnw[c], beta = gnb[c];
    float tg = g_tglob[(size_t)b * CC + c];
    const float* src = g_sraw + ((size_t)b * CC + c) * PS;

    for (int i = tid; i < 38 * 38; i += 256) {
        int yy = i / 38, xx = i - yy * 38;
        int gy = ty0 + yy - 3, gx = tx0 + xx - 3;
        float v = 0.f;
        if ((unsigned)gy < 64u && (unsigned)gx < 64u) {
            float r = src[gy * HS + gx];
            v = fmaxf((r - mean) * rstd * gamma + beta, 0.f);
        }
        sm[i] = v;
    }
    if (tid < 49) kw[tid] = g_tker[((size_t)b * CC + c) * 49 + tid];
    __syncthreads();

    int p = tid * 4;
    int py = p >> 5, px = p & 31;
    float a0 = 0.f, a1 = 0.f, a2 = 0.f, a3 = 0.f;
    #pragma unroll
    for (int ky = 0; ky < 7; ky++) {
        const float* row = &sm[(py + ky) * 38 + px];
        #pragma unroll
        for (int kx = 0; kx < 7; kx++) {
            float w = kw[ky * 7 + kx];
            a0 += w * row[kx];
            a1 += w * row[kx + 1];
            a2 += w * row[kx + 2];
            a3 += w * row[kx + 3];
        }
    }
    const float* ctr = &sm[(py + 3) * 38 + px + 3];
    a0 += tg * ctr[0]; a1 += tg * ctr[1]; a2 += tg * ctr[2]; a3 += tg * ctr[3];

    float* dst = g_corr + ((size_t)b * CC + c) * PS + (ty0 + py) * HS + tx0 + px;
    *(float4*)dst = make_float4(a0, a1, a2, a3);
}

// ---------------- 5) conv3x3 (64->64) implicit GEMM ------------------------
// grid (16 tiles of 16x16 px, 32 batch), 256 threads
// thread: 16 out-channels x 4 px
__global__ void __launch_bounds__(256) k_conv3(const float* __restrict__ wp1) {
    int tile = blockIdx.x, b = blockIdx.y;
    int ty0 = (tile >> 2) * 16, tx0 = (tile & 3) * 16;
    __shared__ float xs[8][18][18];
    __shared__ float wsm[8][9][68];   // [ci][k][o], padded, 16B-aligned rows
    int tid = threadIdx.x;
    int ty = tid >> 6;                 // 0..3 -> outs ty*16..+15
    int tx = tid & 63;
    int r  = tx >> 2;                  // pixel row 0..15
    int c0 = (tx & 3) * 4;             // pixel col base

    float acc[16][4];
    #pragma unroll
    for (int i = 0; i < 16; i++)
        #pragma unroll
        for (int j = 0; j < 4; j++) acc[i][j] = 0.f;

    for (int cc0 = 0; cc0 < CC; cc0 += 8) {
        __syncthreads();
        for (int i = tid; i < 8 * 324; i += 256) {
            int ci = i / 324; int rem = i - ci * 324;
            int yy = rem / 18, xx = rem - yy * 18;
            int gy = ty0 + yy - 1, gx = tx0 + xx - 1;
            float v = 0.f;
            if ((unsigned)gy < 64u && (unsigned)gx < 64u)
                v = g_corr[((size_t)b * CC + cc0 + ci) * PS + gy * HS + gx];
            xs[ci][yy][xx] = v;
        }
        for (int i = tid; i < 8 * 9 * 64; i += 256) {
            int o = i / 72; int rem = i - o * 72;
            int ci = rem / 9, k = rem - ci * 9;
            wsm[ci][k][o] = wp1[o * (CC * 9) + (cc0 + ci) * 9 + k];
        }
        __syncthreads();

        #pragma unroll 2
        for (int ci = 0; ci < 8; ci++) {
            #pragma unroll
            for (int dy = 0; dy < 3; dy++) {
                float xr[6];
                #pragma unroll
                for (int i = 0; i < 6; i++) xr[i] = xs[ci][r + dy][c0 + i];
                #pragma unroll
                for (int dx = 0; dx < 3; dx++) {
                    const float* wrow = &wsm[ci][dy * 3 + dx][ty * 16];
                    #pragma unroll
                    for (int oo = 0; oo < 16; oo++) {
                        float w = wrow[oo];
                        acc[oo][0] += w * xr[dx];
                        acc[oo][1] += w * xr[dx + 1];
                        acc[oo][2] += w * xr[dx + 2];
                        acc[oo][3] += w * xr[dx + 3];
                    }
                }
            }
        }
    }
    #pragma unroll
    for (int oo = 0; oo < 16; oo++) {
        int o = ty * 16 + oo;
        float* dst = g_y + ((size_t)b * CC + o) * PS + (ty0 + r) * HS + tx0 + c0;
        *(float4*)dst = make_float4(acc[oo][0], acc[oo][1], acc[oo][2], acc[oo][3]);
    }
}

// ---------------- 7) final: GN + relu + 1x1 conv to 1 channel --------------
__global__ void k_final(const float* __restrict__ gnw, const float* __restrict__ gnb,
                        const float* __restrict__ w2, const float* __restrict__ b2,
                        float* __restrict__ out) {
    int idx = blockIdx.x * 256 + threadIdx.x;
    if (idx >= BATCH * PS) return;
    int b = idx >> 12, p = idx & (PS - 1);
    const float* yb = g_y + (size_t)b * CC * PS + p;
    float acc = b2[0];
    #pragma unroll 4
    for (int o = 0; o < CC; o++) {
        int bg = b * NGROUP + (o >> 1);
        float v = (yb[(size_t)o * PS] - g_pmean[bg]) * g_prstd[bg] * gnw[o] + gnb[o];
        acc += w2[o] * fmaxf(v, 0.f);
    }
    out[idx] = acc;
}

// ---------------- launch ----------------------------------------------------
extern "C" void kernel_launch(void* const* d_in, const int* in_sizes, int n_in,
                              void* d_out, int out_size) {
    const float* template_feat = (const float*)d_in[0];
    const float* search_feat   = (const float*)d_in[1];
    const float* w_t    = (const float*)d_in[2];
    const float* gn_t_w = (const float*)d_in[3];
    const float* gn_t_b = (const float*)d_in[4];
    const float* w_s    = (const float*)d_in[5];
    const float* gn_s_w = (const float*)d_in[6];
    const float* gn_s_b = (const float*)d_in[7];
    const float* w_p1   = (const float*)d_in[8];
    const float* gn_p_w = (const float*)d_in[9];
    const float* gn_p_b = (const float*)d_in[10];
    const float* w_p2   = (const float*)d_in[11];
    const float* b_p2   = (const float*)d_in[12];
    float* out = (float*)d_out;

    k_template<<<dim3(BATCH, NGROUP), 128>>>(template_feat, w_t, gn_t_w, gn_t_b);
    k_sgemm<<<dim3(PS / 128, BATCH), 256>>>(search_feat, w_s);
    k_stats<<<BATCH * NGROUP, 256>>>(0);
    k_corr<<<dim3(4, CC, BATCH), 256>>>(gn_s_w, gn_s_b);
    k_conv3<<<dim3(16, BATCH), 256>>>(w_p1);
    k_stats<<<BATCH * NGROUP, 256>>>(1);
    k_final<<<(BATCH * PS + 255) / 256, 256>>>(gn_p_w, gn_p_b, w_p2, b_p2, out);
}

// round 2
// speedup vs baseline: 1.2514x; 1.2514x over previous
#include <cuda_runtime.h>
#include <cuda_bf16.h>

#define BATCH 32
#define CIN   256
#define CC    64
#define PT    196     // 14*14
#define HT    14
#define PS    4096    // 64*64
#define HS    64
#define NGROUP 32     // groups of 2 channels

typedef unsigned long long ull;

// ---------------- packed f32x2 helpers (FFMA2 on sm_103a) -------------------
__device__ __forceinline__ ull fma2(ull a, ull b, ull c) {
    ull d;
    asm("fma.rn.f32x2 %0, %1, %2, %3;" : "=l"(d) : "l"(a), "l"(b), "l"(c));
    return d;
}
__device__ __forceinline__ ull pack2(float lo, float hi) {
    ull d;
    asm("mov.b64 %0, {%1, %2};" : "=l"(d) : "f"(lo), "f"(hi));
    return d;
}
__device__ __forceinline__ float2 unpack2(ull v) {
    float2 r;
    asm("mov.b64 {%0, %1}, %2;" : "=f"(r.x), "=f"(r.y) : "l"(v));
    return r;
}

// ---------------- scratch (device globals; allocation-free) ----------------
__device__ float g_sraw[(size_t)BATCH*CC*PS];   // raw search conv1x1 (pre-GN)
__device__ float g_corr[(size_t)BATCH*CC*PS];   // global+local correlation
__device__ float g_y   [(size_t)BATCH*CC*PS];   // conv3x3 output (pre-GN)
__device__ float g_tker[(size_t)BATCH*CC*49];   // pooled 7x7 template kernels
__device__ float g_tglob[(size_t)BATCH*CC];     // template global means
__device__ float g_smean[BATCH*NGROUP];
__device__ float g_srstd[BATCH*NGROUP];
__device__ float g_pmean[BATCH*NGROUP];
__device__ float g_prstd[BATCH*NGROUP];

// ---------------- 1) template branch: conv1x1 + GN + relu + pools ----------
// grid (32 batch, 32 group), 128 threads. FMA2 packs the 2 group channels.
__global__ void k_template(const float* __restrict__ tf, const float* __restrict__ wt,
                           const float* __restrict__ gw, const float* __restrict__ gb) {
    int b = blockIdx.x, g = blockIdx.y;
    __shared__ float tv[392];
    __shared__ ull  wsm[256];            // (w[2g][ci], w[2g+1][ci])
    __shared__ float r1[128], r2[128];
    __shared__ float s_mean, s_rstd;
    int tid = threadIdx.x;
    const float* x = tf + (size_t)b * CIN * PT;

    for (int i = tid; i < 256; i += 128)
        wsm[i] = pack2(wt[(g * 2) * CIN + i], wt[(g * 2 + 1) * CIN + i]);
    __syncthreads();

    for (int p = tid; p < PT; p += 128) {
        ull acc = 0ull;
        #pragma unroll 4
        for (int ci = 0; ci < CIN; ci++) {
            float xv = x[ci * PT + p];
            acc = fma2(wsm[ci], pack2(xv, xv), acc);
        }
        float2 r = unpack2(acc);
        tv[p] = r.x; tv[PT + p] = r.y;
    }
    __syncthreads();

    float s = 0.f, ss = 0.f;
    for (int idx = tid; idx < 392; idx += 128) { float v = tv[idx]; s += v; ss += v * v; }
    r1[tid] = s; r2[tid] = ss;
    __syncthreads();
    for (int o = 64; o > 0; o >>= 1) {
        if (tid < o) { r1[tid] += r1[tid + o]; r2[tid] += r2[tid + o]; }
        __syncthreads();
    }
    if (tid == 0) {
        float m = r1[0] * (1.f / 392.f);
        float var = r2[0] * (1.f / 392.f) - m * m;
        s_mean = m; s_rstd = rsqrtf(var + 1e-5f);
    }
    __syncthreads();

    for (int idx = tid; idx < 392; idx += 128) {
        int c = idx / PT;
        float v = (tv[idx] - s_mean) * s_rstd * gw[g * 2 + c] + gb[g * 2 + c];
        tv[idx] = fmaxf(v, 0.f);
    }
    __syncthreads();

    if (tid < 98) {
        int c = tid / 49, cell = tid - c * 49;
        int i = cell / 7, j = cell - i * 7;
        int base = c * PT + (2 * i) * HT + 2 * j;
        float v = 0.25f * (tv[base] + tv[base + 1] + tv[base + HT] + tv[base + HT + 1]);
        g_tker[((size_t)b * CC + g * 2 + c) * 49 + cell] = v;
    }
    if (tid < 2) {
        float acc = 0.f;
        for (int p = 0; p < PT; p++) acc += tv[tid * PT + p];
        g_tglob[(size_t)b * CC + g * 2 + tid] = acc * (1.f / 196.f);
    }
}

// ---------------- 2) search conv1x1 GEMM: [64,256]x[256,4096] per batch ----
// grid (32 px-tiles of 128, 32 batch), 256 threads, 4 out x 8 px (4 px-pairs)
__global__ void __launch_bounds__(256) k_sgemm(const float* __restrict__ sf,
                                               const float* __restrict__ ws) {
    int b = blockIdx.y;
    int p0 = blockIdx.x * 128;
    __shared__ float As[16][68];    // [k][o], padded
    __shared__ float Bs[16][128];   // [k][p]
    int tid = threadIdx.x;
    int ty = tid >> 4;              // 0..15 -> outs ty*4..+3
    int tx = tid & 15;              // px tx*8..+7
    ull acc2[4][4];
    #pragma unroll
    for (int i = 0; i < 4; i++)
        #pragma unroll
        for (int j = 0; j < 4; j++) acc2[i][j] = 0ull;

    const float* xb = sf + (size_t)b * CIN * PS + p0;

    for (int k0 = 0; k0 < CIN; k0 += 16) {
        __syncthreads();
        for (int i = tid; i < 1024; i += 256) {
            int o = i >> 4, k = i & 15;
            As[k][o] = ws[o * CIN + k0 + k];
        }
        for (int i = tid; i < 512; i += 256) {
            int k = i >> 5, p4 = i & 31;
            ((float4*)Bs[k])[p4] =
                ((const float4*)(xb + (size_t)(k0 + k) * PS))[p4];
        }
        __syncthreads();
        #pragma unroll
        for (int k = 0; k < 16; k++) {
            float4 a = *(const float4*)&As[k][ty * 4];
            ull ap0 = pack2(a.x, a.x), ap1 = pack2(a.y, a.y);
            ull ap2 = pack2(a.z, a.z), ap3 = pack2(a.w, a.w);
            const ull* bp = (const ull*)&Bs[k][tx * 8];
            ull b0 = bp[0], b1 = bp[1], b2 = bp[2], b3 = bp[3];
            acc2[0][0] = fma2(ap0, b0, acc2[0][0]);
            acc2[0][1] = fma2(ap0, b1, acc2[0][1]);
            acc2[0][2] = fma2(ap0, b2, acc2[0][2]);
            acc2[0][3] = fma2(ap0, b3, acc2[0][3]);
            acc2[1][0] = fma2(ap1, b0, acc2[1][0]);
            acc2[1][1] = fma2(ap1, b1, acc2[1][1]);
            acc2[1][2] = fma2(ap1, b2, acc2[1][2]);
            acc2[1][3] = fma2(ap1, b3, acc2[1][3]);
            acc2[2][0] = fma2(ap2, b0, acc2[2][0]);
            acc2[2][1] = fma2(ap2, b1, acc2[2][1]);
            acc2[2][2] = fma2(ap2, b2, acc2[2][2]);
            acc2[2][3] = fma2(ap2, b3, acc2[2][3]);
            acc2[3][0] = fma2(ap3, b0, acc2[3][0]);
            acc2[3][1] = fma2(ap3, b1, acc2[3][1]);
            acc2[3][2] = fma2(ap3, b2, acc2[3][2]);
            acc2[3][3] = fma2(ap3, b3, acc2[3][3]);
        }
    }
    #pragma unroll
    for (int i = 0; i < 4; i++) {
        int o = ty * 4 + i;
        float2 u0 = unpack2(acc2[i][0]), u1 = unpack2(acc2[i][1]);
        float2 u2 = unpack2(acc2[i][2]), u3 = unpack2(acc2[i][3]);
        float* dst = g_sraw + ((size_t)b * CC + o) * PS + p0 + tx * 8;
        *(float4*)dst       = make_float4(u0.x, u0.y, u1.x, u1.y);
        *(float4*)(dst + 4) = make_float4(u2.x, u2.y, u3.x, u3.y);
    }
}

// ---------------- 3/6) GN stats: per (b,group) over 2 channels x 4096 ------
__global__ void k_stats(int which) {
    const float* buf = which ? g_y : g_sraw;
    float* mean = which ? g_pmean : g_smean;
    float* rstd = which ? g_prstd : g_srstd;
    int bg = blockIdx.x;
    const float* x = buf + (size_t)bg * 2 * PS;
    int tid = threadIdx.x;
    float s = 0.f, ss = 0.f;
    for (int i = tid; i < 2 * PS; i += 256) { float v = x[i]; s += v; ss += v * v; }
    __shared__ float r1[256], r2[256];
    r1[tid] = s; r2[tid] = ss;
    __syncthreads();
    for (int o = 128; o > 0; o >>= 1) {
        if (tid < o) { r1[tid] += r1[tid + o]; r2[tid] += r2[tid + o]; }
        __syncthreads();
    }
    if (tid == 0) {
        float m = r1[0] * (1.f / (2.f * PS));
        float var = r2[0] * (1.f / (2.f * PS)) - m * m;
        mean[bg] = m; rstd[bg] = rsqrtf(var + 1e-5f);
    }
}

// ---------------- 4) corr = global + 7x7 depthwise local -------------------
// grid (4 strips of 16x64, 64 ch, 32 batch), 128 threads, 8 px per thread
#define CSTR 70
__global__ void __launch_bounds__(128) k_corr(const float* __restrict__ gnw,
                                              const float* __restrict__ gnb) {
    int strip = blockIdx.x, c = blockIdx.y, b = blockIdx.z;
    int ty0 = strip * 16;
    __shared__ float sm[22 * CSTR];
    __shared__ float kw[49];
    int tid = threadIdx.x;
    int bg = b * NGROUP + (c >> 1);
    float mean = g_smean[bg], rstd = g_srstd[bg];
    float gamma = gnw[c], beta = gnb[c];
    float tg = g_tglob[(size_t)b * CC + c];
    const float* src = g_sraw + ((size_t)b * CC + c) * PS;

    for (int i = tid; i < 22 * CSTR; i += 128) {
        int yy = i / CSTR, xx = i - yy * CSTR;
        int gy = ty0 + yy - 3, gx = xx - 3;
        float v = 0.f;
        if ((unsigned)gy < 64u && (unsigned)gx < 64u) {
            float r = src[gy * HS + gx];
            v = fmaxf((r - mean) * rstd * gamma + beta, 0.f);
        }
        sm[i] = v;
    }
    if (tid < 49) kw[tid] = g_tker[((size_t)b * CC + c) * 49 + tid];
    __syncthreads();

    int row = tid >> 3;            // 0..15
    int colb = (tid & 7) * 8;      // 0,8,..,56
    ull acc2[4] = {0ull, 0ull, 0ull, 0ull};
    ull tgp = pack2(tg, tg);

    #pragma unroll
    for (int ky = 0; ky < 7; ky++) {
        const float* rp = &sm[(row + ky) * CSTR + colb];
        float xr[14];
        #pragma unroll
        for (int i = 0; i < 14; i++) xr[i] = rp[i];
        ull e[7], o[6];
        #pragma unroll
        for (int j = 0; j < 7; j++) e[j] = pack2(xr[2 * j], xr[2 * j + 1]);
        #pragma unroll
        for (int j = 0; j < 6; j++) o[j] = pack2(xr[2 * j + 1], xr[2 * j + 2]);
        #pragma unroll
        for (int kx = 0; kx < 7; kx++) {
            float wv = kw[ky * 7 + kx];
            ull wp = pack2(wv, wv);
            #pragma unroll
            for (int j = 0; j < 4; j++) {
                ull px = (kx & 1) ? o[(kx >> 1) + j] : e[(kx >> 1) + j];
                acc2[j] = fma2(wp, px, acc2[j]);
            }
        }
        if (ky == 3) {
            // global corr: centers start at col offset 3 (odd) -> o[1..4]
            #pragma unroll
            for (int j = 0; j < 4; j++)
                acc2[j] = fma2(tgp, o[1 + j], acc2[j]);
        }
    }

    float2 u0 = unpack2(acc2[0]), u1 = unpack2(acc2[1]);
    float2 u2 = unpack2(acc2[2]), u3 = unpack2(acc2[3]);
    float* dst = g_corr + ((size_t)b * CC + c) * PS + (ty0 + row) * HS + colb;
    *(float4*)dst       = make_float4(u0.x, u0.y, u1.x, u1.y);
    *(float4*)(dst + 4) = make_float4(u2.x, u2.y, u3.x, u3.y);
}

// ---------------- 5) conv3x3 (64->64) implicit GEMM, FMA2 over ch-pairs ----
// grid (16 tiles of 16x16 px, 32 batch), 256 threads
// thread: 8 out-channel-pairs x 4 px
__global__ void __launch_bounds__(256) k_conv3(const float* __restrict__ wp1) {
    int tile = blockIdx.x, b = blockIdx.y;
    int ty0 = (tile >> 2) * 16, tx0 = (tile & 3) * 16;
    __shared__ float xs[8][18][19];   // odd stride: conflict-free-ish
    __shared__ float wsm[8][9][68];   // [ci][k][o], consecutive o -> LDS.64 pairs
    int tid = threadIdx.x;
    int ty = tid >> 6;                 // 0..3 -> outs ty*16..+15
    int tx = tid & 63;
    int r  = tx >> 2;                  // pixel row 0..15
    int c0 = (tx & 3) * 4;             // pixel col base

    ull acc2[8][4];
    #pragma unroll
    for (int i = 0; i < 8; i++)
        #pragma unroll
        for (int j = 0; j < 4; j++) acc2[i][j] = 0ull;

    for (int cc0 = 0; cc0 < CC; cc0 += 8) {
        __syncthreads();
        for (int i = tid; i < 8 * 324; i += 256) {
            int ci = i / 324; int rem = i - ci * 324;
            int yy = rem / 18, xx = rem - yy * 18;
            int gy = ty0 + yy - 1, gx = tx0 + xx - 1;
            float v = 0.f;
            if ((unsigned)gy < 64u && (unsigned)gx < 64u)
                v = g_corr[((size_t)b * CC + cc0 + ci) * PS + gy * HS + gx];
            xs[ci][yy][xx] = v;
        }
        for (int i = tid; i < 8 * 9 * 64; i += 256) {
            int o = i / 72; int rem = i - o * 72;
            int ci = rem / 9, k = rem - ci * 9;
            wsm[ci][k][o] = wp1[o * (CC * 9) + (cc0 + ci) * 9 + k];
        }
        __syncthreads();

        #pragma unroll 2
        for (int ci = 0; ci < 8; ci++) {
            #pragma unroll
            for (int dy = 0; dy < 3; dy++) {
                float xr[6];
                #pragma unroll
                for (int i = 0; i < 6; i++) xr[i] = xs[ci][r + dy][c0 + i];
                ull xb[6];
                #pragma unroll
                for (int i = 0; i < 6; i++) xb[i] = pack2(xr[i], xr[i]);
                #pragma unroll
                for (int dx = 0; dx < 3; dx++) {
                    const ull* wrow = (const ull*)&wsm[ci][dy * 3 + dx][ty * 16];
                    #pragma unroll
                    for (int pp = 0; pp < 8; pp++) {
                        ull w = wrow[pp];
                        acc2[pp][0] = fma2(w, xb[dx],     acc2[pp][0]);
                        acc2[pp][1] = fma2(w, xb[dx + 1], acc2[pp][1]);
                        acc2[pp][2] = fma2(w, xb[dx + 2], acc2[pp][2]);
                        acc2[pp][3] = fma2(w, xb[dx + 3], acc2[pp][3]);
                    }
                }
            }
        }
    }
    #pragma unroll
    for (int pp = 0; pp < 8; pp++) {
        float2 u0 = unpack2(acc2[pp][0]), u1 = unpack2(acc2[pp][1]);
        float2 u2 = unpack2(acc2[pp][2]), u3 = unpack2(acc2[pp][3]);
        int o0 = ty * 16 + 2 * pp;
        float* dst0 = g_y + ((size_t)b * CC + o0) * PS + (ty0 + r) * HS + tx0 + c0;
        *(float4*)dst0        = make_float4(u0.x, u1.x, u2.x, u3.x);
        *(float4*)(dst0 + PS) = make_float4(u0.y, u1.y, u2.y, u3.y);
    }
}

// ---------------- 7) final: GN + relu + 1x1 conv to 1 channel --------------
__global__ void k_final(const float* __restrict__ gnw, const float* __restrict__ gnb,
                        const float* __restrict__ w2, const float* __restrict__ b2,
                        float* __restrict__ out) {
    int idx = blockIdx.x * 256 + threadIdx.x;
    if (idx >= BATCH * PS) return;
    int b = idx >> 12, p = idx & (PS - 1);
    const float* yb = g_y + (size_t)b * CC * PS + p;
    float acc = b2[0];
    #pragma unroll 4
    for (int o = 0; o < CC; o++) {
        int bg = b * NGROUP + (o >> 1);
        float v = (yb[(size_t)o * PS] - g_pmean[bg]) * g_prstd[bg] * gnw[o] + gnb[o];
        acc += w2[o] * fmaxf(v, 0.f);
    }
    out[idx] = acc;
}

// ---------------- launch ----------------------------------------------------
extern "C" void kernel_launch(void* const* d_in, const int* in_sizes, int n_in,
                              void* d_out, int out_size) {
    const float* template_feat = (const float*)d_in[0];
    const float* search_feat   = (const float*)d_in[1];
    const float* w_t    = (const float*)d_in[2];
    const float* gn_t_w = (const float*)d_in[3];
    const float* gn_t_b = (const float*)d_in[4];
    const float* w_s    = (const float*)d_in[5];
    const float* gn_s_w = (const float*)d_in[6];
    const float* gn_s_b = (const float*)d_in[7];
    const float* w_p1   = (const float*)d_in[8];
    const float* gn_p_w = (const float*)d_in[9];
    const float* gn_p_b = (const float*)d_in[10];
    const float* w_p2   = (const float*)d_in[11];
    const float* b_p2   = (const float*)d_in[12];
    float* out = (float*)d_out;

    k_template<<<dim3(BATCH, NGROUP), 128>>>(template_feat, w_t, gn_t_w, gn_t_b);
    k_sgemm<<<dim3(PS / 128, BATCH), 256>>>(search_feat, w_s);
    k_stats<<<BATCH * NGROUP, 256>>>(0);
    k_corr<<<dim3(4, CC, BATCH), 128>>>(gn_s_w, gn_s_b);
    k_conv3<<<dim3(16, BATCH), 256>>>(w_p1);
    k_stats<<<BATCH * NGROUP, 256>>>(1);
    k_final<<<(BATCH * PS + 255) / 256, 256>>>(gn_p_w, gn_p_b, w_p2, b_p2, out);
}